// round 13
// baseline (speedup 1.0000x reference)
#include <cuda_runtime.h>

#define RB 131072
#define RT 6
#define RV 31
#define NJP 16            // j-pairs; j=31 zero-padded
#define XS  (RT * RV)     // 186, row stride of inp [B,T,V]
#define CTAB 64           // threads per CTA
#define EPT 2             // batch elements per thread
#define BLKE (CTAB * EPT) // 128 batch elems per CTA
#define BLKF (BLKE * RV)  // 3968 floats per (t, CTA) block
#define BLKF4 (BLKF / 4)  // 992 float4 chunks
#define PLANE ((size_t)RB * RV)

// Inter-layer activation scratch, TIME-MAJOR [T][B][V].
__device__ float g_scratch[(size_t)RT * RB * RV];

typedef unsigned long long u64;

__device__ __forceinline__ u64 pkdup(float a) {
    u64 r;
    asm("mov.b64 %0, {%1, %1};" : "=l"(r) : "f"(a));
    return r;
}
__device__ __forceinline__ u64 pk2(float a, float b) {
    u64 r;
    asm("mov.b64 %0, {%1, %2};" : "=l"(r) : "f"(a), "f"(b));
    return r;
}
__device__ __forceinline__ void upk2(u64 v, float& x, float& y) {
    asm("mov.b64 {%0, %1}, %2;" : "=f"(x), "=f"(y) : "l"(v));
}
__device__ __forceinline__ u64 ffma2(u64 a, u64 b, u64 c) {
    u64 d;
    asm("fma.rn.f32x2 %0, %1, %2, %3;" : "=l"(d) : "l"(a), "l"(b), "l"(c));
    return d;
}
// tanh(x) = 1 - 2/(2^(x*2*log2e)+1); 1 FMUL + MUFU.EX2 + FADD + MUFU.RCP + FMUL + FADD
__device__ __forceinline__ float tanh_fast(float x) {
    float e = exp2f(x * 2.885390081777927f);
    return 1.0f - __fdividef(2.0f, e + 1.0f);
}

// ---- cp.async helpers --------------------------------------------------
__device__ __forceinline__ unsigned su32(const void* p) {
    return (unsigned)__cvta_generic_to_shared(p);
}
__device__ __forceinline__ void cpa16(unsigned s, const void* g) {
    asm volatile("cp.async.ca.shared.global [%0], [%1], 16;" :: "r"(s), "l"(g));
}
__device__ __forceinline__ void cpa4(unsigned s, const void* g) {
    asm volatile("cp.async.ca.shared.global [%0], [%1], 4;" :: "r"(s), "l"(g));
}
#define CP_COMMIT() asm volatile("cp.async.commit_group;")
#define CP_WAIT0()  asm volatile("cp.async.wait_group 0;" ::: "memory")

// flat async prefetch: chunk c = tid + 64*it over float4 chunks
__device__ __forceinline__ void pf_flat(float* sdst, const float* gsrc, int tid) {
    unsigned sb = su32(sdst);
#pragma unroll
    for (int it = 0; it < 16; ++it) {
        int i = tid + CTAB * it;
        if (i < BLKF4) cpa16(sb + 16u * i, (const float4*)gsrc + i);
    }
}
// strided prefetch from inp [B,T,V], SAME chunk mapping as pf_flat/st_flat:
// chunk c covers floats 4c..4c+3; per chunk one div, then carry-increment.
__device__ __forceinline__ void pf_strided(float* sdst, const float* gsrc, int tid) {
    unsigned sb = su32(sdst);
#pragma unroll
    for (int it = 0; it < 16; ++it) {
        int c = tid + CTAB * it;
        if (c < BLKF4) {
            int f = 4 * c;
            int r = f / RV;
            int cc = f - r * RV;
#pragma unroll
            for (int e = 0; e < 4; ++e) {
                cpa4(sb + 4u * (f + e), gsrc + r * XS + cc);
                if (++cc == RV) { cc = 0; ++r; }
            }
        }
    }
}
// coalesced coop store, SAME chunk mapping (same-thread ordering vs prefetch)
__device__ __forceinline__ void st_flat(float* gdst, const float* ssrc, int tid) {
#pragma unroll
    for (int it = 0; it < 16; ++it) {
        int i = tid + CTAB * it;
        if (i < BLKF4) ((float4*)gdst)[i] = ((const float4*)ssrc)[i];
    }
}

// w2[k*NJP+jp] = { {Wih[j0,k],Wih[j1,k]}, {Whh[j0,k],Whh[j1,k]} }, j1==31 -> 0
__device__ __forceinline__ void fill_w(ulonglong2* w2, u64* bias2,
                                       const float* __restrict__ Wih,
                                       const float* __restrict__ Whh,
                                       const float* __restrict__ bih,
                                       const float* __restrict__ bhh,
                                       int tid)
{
    for (int i = tid; i < RV * NJP; i += CTAB) {
        int k = i / NJP, jp = i - k * NJP;
        int j0 = 2 * jp, j1 = j0 + 1;
        float a0 = Wih[j0 * RV + k];
        float a1 = (j1 < RV) ? Wih[j1 * RV + k] : 0.0f;
        float c0 = Whh[j0 * RV + k];
        float c1 = (j1 < RV) ? Whh[j1 * RV + k] : 0.0f;
        w2[i].x = pk2(a0, a1);
        w2[i].y = pk2(c0, c1);
    }
    if (tid < NJP) {
        int j0 = 2 * tid, j1 = j0 + 1;
        bias2[tid] = pk2(bih[j0] + bhh[j0],
                         (j1 < RV) ? (bih[j1] + bhh[j1]) : 0.0f);
    }
}

// dual-element step: each weight LDS.128 feeds 4 FFMA2
__device__ __forceinline__ void rnn_step2(u64* acc0, u64* acc1,
                                          const float* xr0, const float* xr1,
                                          const float* ha, const float* hb,
                                          const ulonglong2* w2, const u64* bias2)
{
#pragma unroll
    for (int jp = 0; jp < NJP; ++jp) { acc0[jp] = bias2[jp]; acc1[jp] = bias2[jp]; }
#pragma unroll
    for (int k = 0; k < RV; ++k) {
        const u64 x0 = pkdup(xr0[k]);
        const u64 h0 = pkdup(ha[k]);
        const u64 x1 = pkdup(xr1[k]);
        const u64 h1 = pkdup(hb[k]);
        const ulonglong2* wr = w2 + k * NJP;
#pragma unroll
        for (int jp = 0; jp < NJP; ++jp) {
            ulonglong2 w = wr[jp];               // one broadcast LDS.128
            acc0[jp] = ffma2(w.x, x0, acc0[jp]);
            acc0[jp] = ffma2(w.y, h0, acc0[jp]);
            acc1[jp] = ffma2(w.x, x1, acc1[jp]);
            acc1[jp] = ffma2(w.y, h1, acc1[jp]);
        }
    }
}

// One RNN layer over all T steps; two batch elements per thread. ONE sync/t.
__global__ void __launch_bounds__(CTAB, 4)
rnn_layer(const float* xin_ext, int use_ext_in,
          const float* __restrict__ h0g,
          const float* __restrict__ Wih, const float* __restrict__ Whh,
          const float* __restrict__ bih, const float* __restrict__ bhh)
{
    __shared__ ulonglong2 w2[RV * NJP];     // 7936 B
    __shared__ u64 bias2[NJP];
    __shared__ float xb0[BLKF];             // double-buffered staging
    __shared__ float xb1[BLKF];

    const int tid = threadIdx.x;
    fill_w(w2, bias2, Wih, Whh, bih, bhh, tid);

    const size_t blk0 = (size_t)blockIdx.x * BLKE;
    const int r0 = 2 * tid, r1 = 2 * tid + 1;

    // h0 -> xb1 (will be overwritten by prefetch of x[1] at t=0)
    pf_flat(xb1, h0g + blk0 * RV, tid);
    CP_COMMIT(); CP_WAIT0();
    __syncthreads();

    float ha[RV], hb[RV];
#pragma unroll
    for (int j = 0; j < RV; ++j) { ha[j] = xb1[r0 * RV + j]; hb[j] = xb1[r1 * RV + j]; }
    __syncthreads();          // own-row h reads done before xb1 reused

    // x[0] -> xb0
    if (use_ext_in) pf_strided(xb0, xin_ext + blk0 * XS, tid);
    else            pf_flat(xb0, g_scratch + blk0 * RV, tid);
    CP_COMMIT(); CP_WAIT0();
    __syncthreads();

#pragma unroll 1
    for (int t = 0; t < RT; ++t) {
        float* cur = ((t & 1) == 0) ? xb0 : xb1;
        float* nxt = ((t & 1) == 0) ? xb1 : xb0;

        // prefetch x[t+1] into nxt; same-thread chunk mapping as st_flat(t-1)
        if (t + 1 < RT) {
            if (use_ext_in)
                pf_strided(nxt, xin_ext + blk0 * XS + (t + 1) * RV, tid);
            else
                pf_flat(nxt, g_scratch + (t + 1) * PLANE + blk0 * RV, tid);
        }
        CP_COMMIT();

        u64 acc0[NJP], acc1[NJP];
        rnn_step2(acc0, acc1, cur + r0 * RV, cur + r1 * RV, ha, hb, w2, bias2);

        // tanh writeback to OWN rows of cur
#pragma unroll
        for (int jp = 0; jp < NJP; ++jp) {
            float a0, a1, b0, b1;
            upk2(acc0[jp], a0, a1);
            upk2(acc1[jp], b0, b1);
            int j0 = 2 * jp, j1 = j0 + 1;
            float v = tanh_fast(a0);
            ha[j0] = v; cur[r0 * RV + j0] = v;
            v = tanh_fast(b0);
            hb[j0] = v; cur[r1 * RV + j0] = v;
            if (j1 < RV) {
                v = tanh_fast(a1);
                ha[j1] = v; cur[r0 * RV + j1] = v;
                v = tanh_fast(b1);
                hb[j1] = v; cur[r1 * RV + j1] = v;
            }
        }
        CP_WAIT0();
        __syncthreads();     // publish: nxt chunks + everyone's cur writebacks
        st_flat(g_scratch + t * PLANE + blk0 * RV, cur, tid);
        // no second sync: st_flat chunks == prefetch chunks (same thread),
        // and next-t prefetch into THIS buffer is ordered by next sync anyway
    }
}

// Layer 2 recurrence (no activation stores) + linear + tanh + softmax.
__global__ void __launch_bounds__(CTAB, 4)
rnn_final(const float* __restrict__ h0g,
          const float* __restrict__ Wih, const float* __restrict__ Whh,
          const float* __restrict__ bih, const float* __restrict__ bhh,
          const float* __restrict__ Wlin, const float* __restrict__ blin,
          float* __restrict__ out)
{
    __shared__ ulonglong2 w2[RV * NJP];
    __shared__ u64 bias2[NJP];
    __shared__ u64 wl[RV * NJP];
    __shared__ u64 bl[NJP];
    __shared__ float xb0[BLKF];
    __shared__ float xb1[BLKF];

    const int tid = threadIdx.x;
    fill_w(w2, bias2, Wih, Whh, bih, bhh, tid);
    for (int i = tid; i < RV * NJP; i += CTAB) {
        int k = i / NJP, jp = i - k * NJP;
        int j0 = 2 * jp, j1 = j0 + 1;
        wl[i] = pk2(Wlin[j0 * RV + k], (j1 < RV) ? Wlin[j1 * RV + k] : 0.0f);
    }
    if (tid < NJP) {
        int j0 = 2 * tid, j1 = j0 + 1;
        bl[tid] = pk2(blin[j0], (j1 < RV) ? blin[j1] : 0.0f);
    }

    const size_t blk0 = (size_t)blockIdx.x * BLKE;
    const int r0 = 2 * tid, r1 = 2 * tid + 1;

    pf_flat(xb1, h0g + blk0 * RV, tid);
    CP_COMMIT(); CP_WAIT0();
    __syncthreads();

    float ha[RV], hb[RV];
#pragma unroll
    for (int j = 0; j < RV; ++j) { ha[j] = xb1[r0 * RV + j]; hb[j] = xb1[r1 * RV + j]; }
    __syncthreads();

    pf_flat(xb0, g_scratch + blk0 * RV, tid);
    CP_COMMIT(); CP_WAIT0();
    __syncthreads();

#pragma unroll 1
    for (int t = 0; t < RT; ++t) {
        float* cur = ((t & 1) == 0) ? xb0 : xb1;
        float* nxt = ((t & 1) == 0) ? xb1 : xb0;

        if (t + 1 < RT)
            pf_flat(nxt, g_scratch + (t + 1) * PLANE + blk0 * RV, tid);
        CP_COMMIT();

        u64 acc0[NJP], acc1[NJP];
        rnn_step2(acc0, acc1, cur + r0 * RV, cur + r1 * RV, ha, hb, w2, bias2);

#pragma unroll
        for (int jp = 0; jp < NJP; ++jp) {
            float a0, a1, b0, b1;
            upk2(acc0[jp], a0, a1);
            upk2(acc1[jp], b0, b1);
            ha[2 * jp] = tanh_fast(a0);
            hb[2 * jp] = tanh_fast(b0);
            if (2 * jp + 1 < RV) {
                ha[2 * jp + 1] = tanh_fast(a1);
                hb[2 * jp + 1] = tanh_fast(b1);
            }
        }
        CP_WAIT0();
        __syncthreads();
    }

    // linear + tanh
    u64 l0[NJP], l1[NJP];
#pragma unroll
    for (int jp = 0; jp < NJP; ++jp) { l0[jp] = bl[jp]; l1[jp] = bl[jp]; }
#pragma unroll
    for (int k = 0; k < RV; ++k) {
        const u64 h0d = pkdup(ha[k]);
        const u64 h1d = pkdup(hb[k]);
        const u64* wr = wl + k * NJP;
#pragma unroll
        for (int jp = 0; jp < NJP; ++jp) {
            u64 w = wr[jp];
            l0[jp] = ffma2(w, h0d, l0[jp]);
            l1[jp] = ffma2(w, h1d, l1[jp]);
        }
    }

    float ya[2 * NJP], yb[2 * NJP];
#pragma unroll
    for (int jp = 0; jp < NJP; ++jp) {
        float a0, a1, b0, b1;
        upk2(l0[jp], a0, a1);
        upk2(l1[jp], b0, b1);
        ya[2 * jp] = tanh_fast(a0);
        yb[2 * jp] = tanh_fast(b0);
        ya[2 * jp + 1] = (2 * jp + 1 < RV) ? tanh_fast(a1) : -1e30f;
        yb[2 * jp + 1] = (2 * jp + 1 < RV) ? tanh_fast(b1) : -1e30f;
    }

    // softmax per element, stage into xb0, coalesced store
    {
        float m = ya[0];
#pragma unroll
        for (int j = 1; j < RV; ++j) m = fmaxf(m, ya[j]);
        float s = 0.0f;
#pragma unroll
        for (int j = 0; j < RV; ++j) { ya[j] = __expf(ya[j] - m); s += ya[j]; }
        float inv = __fdividef(1.0f, s);
#pragma unroll
        for (int j = 0; j < RV; ++j) xb0[r0 * RV + j] = ya[j] * inv;
    }
    {
        float m = yb[0];
#pragma unroll
        for (int j = 1; j < RV; ++j) m = fmaxf(m, yb[j]);
        float s = 0.0f;
#pragma unroll
        for (int j = 0; j < RV; ++j) { yb[j] = __expf(yb[j] - m); s += yb[j]; }
        float inv = __fdividef(1.0f, s);
#pragma unroll
        for (int j = 0; j < RV; ++j) xb0[r1 * RV + j] = yb[j] * inv;
    }
    __syncthreads();
    st_flat(out + blk0 * RV, xb0, tid);
}

extern "C" void kernel_launch(void* const* d_in, const int* in_sizes, int n_in,
                              void* d_out, int out_size)
{
    const float* inp  = (const float*)d_in[0];  // [B,T,V]
    const float* h0   = (const float*)d_in[1];  // [L,B,V]
    const float* Wih  = (const float*)d_in[2];  // [L,V,V]
    const float* Whh  = (const float*)d_in[3];  // [L,V,V]
    const float* bih  = (const float*)d_in[4];  // [L,V]
    const float* bhh  = (const float*)d_in[5];  // [L,V]
    const float* Wlin = (const float*)d_in[6];  // [V,V]
    const float* blin = (const float*)d_in[7];  // [V]
    float* out = (float*)d_out;                 // [B,V]

    (void)in_sizes; (void)n_in; (void)out_size;

    const dim3 grid(RB / BLKE), block(CTAB);    // 1024 x 64

    rnn_layer<<<grid, block>>>(inp, 1, h0, Wih, Whh, bih, bhh);
    rnn_layer<<<grid, block>>>(nullptr, 0, h0 + (size_t)RB * RV,
                               Wih + RV * RV, Whh + RV * RV,
                               bih + RV, bhh + RV);
    rnn_final<<<grid, block>>>(h0 + 2 * (size_t)RB * RV,
                               Wih + 2 * RV * RV, Whh + 2 * RV * RV,
                               bih + 2 * RV, bhh + 2 * RV,
                               Wlin, blin, out);
}